// round 1
// baseline (speedup 1.0000x reference)
#include <cuda_runtime.h>
#include <cstdint>

#define BB 64
#define TT 512
#define DD 256
#define UU 512
#define NCTA 128
#define WSTR (UU + 4)

// Scratch (static device allocations are allowed; no cudaMalloc anywhere).
__device__ float g_xp[3][TT][BB][UU];     // input projections, time-major [g][t][b][u]
__device__ float g_hbuf[2][BB * UU];      // ping-pong hidden state
__device__ unsigned g_count;              // grid barrier counter (reset each launch)

// ---- packed f32x2 helpers (full-rate fp32 on sm_103a) ----
__device__ __forceinline__ void fma2(unsigned long long &d, unsigned long long a,
                                     unsigned long long b) {
    asm("fma.rn.f32x2 %0, %1, %2, %0;" : "+l"(d) : "l"(a), "l"(b));
}
__device__ __forceinline__ float2 upk(unsigned long long v) {
    float2 r;
    asm("mov.b64 {%0, %1}, %2;" : "=f"(r.x), "=f"(r.y) : "l"(v));
    return r;
}

__device__ __forceinline__ float fsig(float x) {
    return __fdividef(1.0f, 1.0f + __expf(-x));
}
__device__ __forceinline__ float ftanh(float x) {
    float e = __expf(-2.0f * fabsf(x));           // always <= 1, no overflow
    float r = __fdividef(1.0f - e, 1.0f + e);
    return copysignf(r, x);
}

// ============================================================================
// Phase 1: xp[g][t][b][u] = x[b,t,:] @ w_xg[:,u] + b_g[u]
// Tile: one t (64 b-rows) x 64 u-cols x 3 gates per CTA, BK=32, f32x2 over u.
// ============================================================================
__global__ void __launch_bounds__(256, 2) proj_kernel(
    const float* __restrict__ x,
    const float* __restrict__ wxi, const float* __restrict__ wxf,
    const float* __restrict__ wxc,
    const float* __restrict__ bi, const float* __restrict__ bf,
    const float* __restrict__ bc) {
    __shared__ __align__(16) float xs[64][33];
    __shared__ __align__(16) float ws[3][32][64];

    const int tid = threadIdx.x;
    const int t = blockIdx.y;
    const int ub = blockIdx.x * 64;

    // Reset the grid barrier for the recurrent kernel (once per launch).
    if (blockIdx.x == 0 && blockIdx.y == 0 && tid == 0) g_count = 0u;

    const int ug = tid & 15;     // u group: 16 groups of 4 cols
    const int bg = tid >> 4;     // b group: 16 groups of 4 rows
    const int ul = ug << 2;
    const int b0 = bg << 2;

    unsigned long long acc[3][4][2];
#pragma unroll
    for (int g = 0; g < 3; ++g)
#pragma unroll
        for (int i = 0; i < 4; ++i) { acc[g][i][0] = 0ull; acc[g][i][1] = 0ull; }

    for (int k0 = 0; k0 < DD; k0 += 32) {
#pragma unroll
        for (int i = 0; i < 8; ++i) {            // 64*32 / 256
            int idx = tid + i * 256;
            int bb = idx >> 5, kk = idx & 31;
            xs[bb][kk] = x[(bb * TT + t) * DD + k0 + kk];
        }
#pragma unroll
        for (int i = 0; i < 24; ++i) {           // 3*32*64 / 256
            int idx = tid + i * 256;
            int g = idx >> 11, r = idx & 2047, kk = r >> 6, uu = r & 63;
            const float* w = (g == 0) ? wxi : ((g == 1) ? wxf : wxc);
            ws[g][kk][uu] = w[(k0 + kk) * UU + ub + uu];
        }
        __syncthreads();
#pragma unroll
        for (int kk = 0; kk < 32; ++kk) {
            unsigned long long xb[4];
#pragma unroll
            for (int i = 0; i < 4; ++i) {
                unsigned xv = __float_as_uint(xs[b0 + i][kk]);
                asm("mov.b64 %0, {%1, %1};" : "=l"(xb[i]) : "r"(xv));
            }
#pragma unroll
            for (int g = 0; g < 3; ++g) {
                const ulonglong2 wv = *(const ulonglong2*)&ws[g][kk][ul];
#pragma unroll
                for (int i = 0; i < 4; ++i) {
                    fma2(acc[g][i][0], xb[i], wv.x);
                    fma2(acc[g][i][1], xb[i], wv.y);
                }
            }
        }
        __syncthreads();
    }

    const float* biases[3] = {bi, bf, bc};
#pragma unroll
    for (int g = 0; g < 3; ++g) {
        float2 bv0 = *(const float2*)&biases[g][ub + ul];
        float2 bv1 = *(const float2*)&biases[g][ub + ul + 2];
#pragma unroll
        for (int i = 0; i < 4; ++i) {
            float2 r0 = upk(acc[g][i][0]);
            float2 r1 = upk(acc[g][i][1]);
            r0.x += bv0.x; r0.y += bv0.y;
            r1.x += bv1.x; r1.y += bv1.y;
            float* dst = &g_xp[g][t][b0 + i][ub + ul];
            *(float2*)dst = r0;
            *(float2*)(dst + 2) = r1;
        }
    }
}

// ============================================================================
// Phase 2: persistent recurrent kernel.
// 128 CTAs x 256 threads. CTA owns 4 U-columns (all 3 gates) with weights
// transposed in smem. Thread = (b, c): one batch row, one column; c-state in
// a register; f32x2 packs over K (even/odd k in the two lanes), horizontal
// add once per dot. Software grid barrier per step (monotonic counter).
// ============================================================================
__global__ void __launch_bounds__(256, 1) lstm_kernel(
    const float* __restrict__ whi, const float* __restrict__ whf,
    const float* __restrict__ whc,
    const float* __restrict__ h0, const float* __restrict__ c0,
    float* __restrict__ out) {
    __shared__ __align__(16) float Wt[3][4][WSTR];   // [gate][col][k], padded

    const int tid = threadIdx.x;
    const int c = tid & 3;
    const int b = tid >> 2;
    const int u0 = blockIdx.x * 4;
    const int u = u0 + c;

    {
        const float* wsrc[3] = {whi, whf, whc};
#pragma unroll
        for (int g = 0; g < 3; ++g)
            for (int i = tid; i < 4 * UU; i += 256) {
                int cc = i & 3, k = i >> 2;
                Wt[g][cc][k] = wsrc[g][k * UU + u0 + cc];
            }
    }
    float cst = c0[b * UU + u];
    __syncthreads();

    const ulonglong2* w0 = (const ulonglong2*)&Wt[0][c][0];
    const ulonglong2* w1 = (const ulonglong2*)&Wt[1][c][0];
    const ulonglong2* w2 = (const ulonglong2*)&Wt[2][c][0];
    const float* xpi = &g_xp[0][0][b][u];
    const float* xpf = &g_xp[1][0][b][u];
    const float* xpc = &g_xp[2][0][b][u];
    float* orow = out + (size_t)(b * TT) * UU + u;

    for (int t = 0; t < TT; ++t) {
        // issue xproj loads early (DRAM latency hidden under the dot loop)
        float pi = xpi[t * (BB * UU)];
        float pf = xpf[t * (BB * UU)];
        float pc = xpc[t * (BB * UU)];

        const float* hsrc =
            (t == 0) ? (h0 + b * UU) : (&g_hbuf[(t + 1) & 1][0] + b * UU);
        const ulonglong2* hr = (const ulonglong2*)hsrc;

        unsigned long long a0 = 0ull, a1 = 0ull, a2 = 0ull;
#pragma unroll 8
        for (int k4 = 0; k4 < UU / 4; ++k4) {
            ulonglong2 hv = hr[k4];
            ulonglong2 v0 = w0[k4];
            ulonglong2 v1 = w1[k4];
            ulonglong2 v2 = w2[k4];
            fma2(a0, hv.x, v0.x); fma2(a1, hv.x, v1.x); fma2(a2, hv.x, v2.x);
            fma2(a0, hv.y, v0.y); fma2(a1, hv.y, v1.y); fma2(a2, hv.y, v2.y);
        }
        float2 s0 = upk(a0), s1 = upk(a1), s2 = upk(a2);
        float ig = fsig(pi + s0.x + s0.y);
        float fg = fsig(pf + s1.x + s1.y);
        float cin = ftanh(pc + s2.x + s2.y);
        cst = fg * cst + ig * cin;
        float hn = ftanh(cst);

        g_hbuf[t & 1][b * UU + u] = hn;
        orow[(size_t)t * UU] = hn;

        if (t < TT - 1) {
            __threadfence();           // release h writes device-wide
            __syncthreads();
            if (tid == 0) {
                atomicAdd(&g_count, 1u);
                unsigned target = (unsigned)(t + 1) * NCTA;
                while (*(volatile unsigned*)&g_count < target) { }
                __threadfence();       // acquire before releasing the CTA
            }
            __syncthreads();
        }
    }
}

extern "C" void kernel_launch(void* const* d_in, const int* in_sizes, int n_in,
                              void* d_out, int out_size) {
    const float* x   = (const float*)d_in[0];
    const float* wxi = (const float*)d_in[1];
    const float* wxf = (const float*)d_in[2];
    const float* wxc = (const float*)d_in[3];
    const float* whi = (const float*)d_in[4];
    const float* whf = (const float*)d_in[5];
    const float* whc = (const float*)d_in[6];
    const float* bi  = (const float*)d_in[7];
    const float* bf  = (const float*)d_in[8];
    const float* bc  = (const float*)d_in[9];
    const float* h0  = (const float*)d_in[10];
    const float* c0  = (const float*)d_in[11];
    float* out = (float*)d_out;

    proj_kernel<<<dim3(8, TT), 256>>>(x, wxi, wxf, wxc, bi, bf, bc);
    lstm_kernel<<<NCTA, 256>>>(whi, whf, whc, h0, c0, out);
}

// round 2
// speedup vs baseline: 1.2207x; 1.2207x over previous
#include <cuda_runtime.h>
#include <cstdint>

#define BB 64
#define TT 512
#define DD 256
#define UU 512
#define NCTA 128
#define WROW 520   // weight row stride (floats): 520 % 32 == 8 -> 4 c-rows on distinct banks

// Scratch (static device arrays; no cudaMalloc anywhere).
__device__ float g_xp[3][TT][BB][UU];     // input projections, time-major [g][t][b][u]
__device__ float g_hbuf[2][BB * UU];      // ping-pong hidden state
__device__ unsigned g_count;              // grid barrier counter (reset each launch)

// ---- packed f32x2 helpers (full-rate fp32 on sm_103a) ----
__device__ __forceinline__ void fma2(unsigned long long &d, unsigned long long a,
                                     unsigned long long b) {
    asm("fma.rn.f32x2 %0, %1, %2, %0;" : "+l"(d) : "l"(a), "l"(b));
}
__device__ __forceinline__ float2 upk(unsigned long long v) {
    float2 r;
    asm("mov.b64 {%0, %1}, %2;" : "=f"(r.x), "=f"(r.y) : "l"(v));
    return r;
}
// 16B L2-only (coherent) global load, repacked as 2x f32x2
__device__ __forceinline__ ulonglong2 ldcg_u2(const float* p) {
    float4 v = __ldcg((const float4*)p);
    ulonglong2 r;
    asm("mov.b64 %0, {%1, %2};" : "=l"(r.x) : "f"(v.x), "f"(v.y));
    asm("mov.b64 %0, {%1, %2};" : "=l"(r.y) : "f"(v.z), "f"(v.w));
    return r;
}

__device__ __forceinline__ float fsig(float x) {
    return __fdividef(1.0f, 1.0f + __expf(-x));
}
__device__ __forceinline__ float ftanh(float x) {
    float e = __expf(-2.0f * fabsf(x));
    float r = __fdividef(1.0f - e, 1.0f + e);
    return copysignf(r, x);
}

// ============================================================================
// Phase 1: xp[g][t][b][u] = x[b,t,:] @ w_xg[:,u] + b_g[u]   (unchanged)
// ============================================================================
__global__ void __launch_bounds__(256, 2) proj_kernel(
    const float* __restrict__ x,
    const float* __restrict__ wxi, const float* __restrict__ wxf,
    const float* __restrict__ wxc,
    const float* __restrict__ bi, const float* __restrict__ bf,
    const float* __restrict__ bc) {
    __shared__ __align__(16) float xs[64][33];
    __shared__ __align__(16) float ws[3][32][64];

    const int tid = threadIdx.x;
    const int t = blockIdx.y;
    const int ub = blockIdx.x * 64;

    if (blockIdx.x == 0 && blockIdx.y == 0 && tid == 0) g_count = 0u;

    const int ug = tid & 15;
    const int bg = tid >> 4;
    const int ul = ug << 2;
    const int b0 = bg << 2;

    unsigned long long acc[3][4][2];
#pragma unroll
    for (int g = 0; g < 3; ++g)
#pragma unroll
        for (int i = 0; i < 4; ++i) { acc[g][i][0] = 0ull; acc[g][i][1] = 0ull; }

    for (int k0 = 0; k0 < DD; k0 += 32) {
#pragma unroll
        for (int i = 0; i < 8; ++i) {
            int idx = tid + i * 256;
            int bb = idx >> 5, kk = idx & 31;
            xs[bb][kk] = x[(bb * TT + t) * DD + k0 + kk];
        }
#pragma unroll
        for (int i = 0; i < 24; ++i) {
            int idx = tid + i * 256;
            int g = idx >> 11, r = idx & 2047, kk = r >> 6, uu = r & 63;
            const float* w = (g == 0) ? wxi : ((g == 1) ? wxf : wxc);
            ws[g][kk][uu] = w[(k0 + kk) * UU + ub + uu];
        }
        __syncthreads();
#pragma unroll
        for (int kk = 0; kk < 32; ++kk) {
            unsigned long long xb[4];
#pragma unroll
            for (int i = 0; i < 4; ++i) {
                unsigned xv = __float_as_uint(xs[b0 + i][kk]);
                asm("mov.b64 %0, {%1, %1};" : "=l"(xb[i]) : "r"(xv));
            }
#pragma unroll
            for (int g = 0; g < 3; ++g) {
                const ulonglong2 wv = *(const ulonglong2*)&ws[g][kk][ul];
#pragma unroll
                for (int i = 0; i < 4; ++i) {
                    fma2(acc[g][i][0], xb[i], wv.x);
                    fma2(acc[g][i][1], xb[i], wv.y);
                }
            }
        }
        __syncthreads();
    }

    const float* biases[3] = {bi, bf, bc};
#pragma unroll
    for (int g = 0; g < 3; ++g) {
        float2 bv0 = *(const float2*)&biases[g][ub + ul];
        float2 bv1 = *(const float2*)&biases[g][ub + ul + 2];
#pragma unroll
        for (int i = 0; i < 4; ++i) {
            float2 r0 = upk(acc[g][i][0]);
            float2 r1 = upk(acc[g][i][1]);
            r0.x += bv0.x; r0.y += bv0.y;
            r1.x += bv1.x; r1.y += bv1.y;
            float* dst = &g_xp[g][t][b0 + i][ub + ul];
            *(float2*)dst = r0;
            *(float2*)(dst + 2) = r1;
        }
    }
}

// ============================================================================
// Phase 2: persistent recurrent kernel, 4-b weight reuse + K-split reduction.
// 128 CTAs x 256 threads. CTA owns 4 U-columns x 3 gates.
// k-loop role:  tid -> c = tid&3 (column), bg = (tid>>2)&15 (4 b-rows),
//               ks = tid>>6 (128-wide K chunk).
// gate role:    tid -> b2 = tid>>2, c2 = tid&3; cell state in a register.
// ============================================================================
__global__ void __launch_bounds__(256, 1) lstm_kernel(
    const float* __restrict__ whi, const float* __restrict__ whf,
    const float* __restrict__ whc,
    const float* __restrict__ h0, const float* __restrict__ c0,
    float* __restrict__ out) {
    __shared__ __align__(16) float W2[3][4][WROW];       // [gate][col][k]
    __shared__ __align__(16) float red[4][3][4][16][5];  // [ks][g][i][bg][c(+pad)]

    const int tid = threadIdx.x;
    const int u0 = blockIdx.x * 4;
    // k-loop roles
    const int c  = tid & 3;
    const int bg = (tid >> 2) & 15;
    const int ks = tid >> 6;
    // gate roles
    const int b2 = tid >> 2;
    const int c2 = tid & 3;
    const int u  = u0 + c2;

    {
        const float* wsrc[3] = {whi, whf, whc};
#pragma unroll
        for (int g = 0; g < 3; ++g)
            for (int i = tid; i < 4 * UU; i += 256) {
                int cc = i & 3, k = i >> 2;
                W2[g][cc][k] = wsrc[g][k * UU + u0 + cc];
            }
    }
    float cst = c0[b2 * UU + u];
    __syncthreads();

    const ulonglong2* wp0 = (const ulonglong2*)&W2[0][c][ks * 128];
    const ulonglong2* wp1 = (const ulonglong2*)&W2[1][c][ks * 128];
    const ulonglong2* wp2 = (const ulonglong2*)&W2[2][c][ks * 128];
    const int hoff = (bg * 4) * UU + ks * 128;   // this thread's h base offset
    const float* xpi = &g_xp[0][0][b2][u];
    const float* xpf = &g_xp[1][0][b2][u];
    const float* xpc = &g_xp[2][0][b2][u];
    float* orow = out + (size_t)(b2 * TT) * UU + u;

    for (int t = 0; t < TT; ++t) {
        // prefetch this thread's input projections (gate role)
        float pi = __ldcg(xpi + t * (BB * UU));
        float pf = __ldcg(xpf + t * (BB * UU));
        float pc = __ldcg(xpc + t * (BB * UU));

        const float* hsrc = (t == 0) ? h0 : &g_hbuf[(t + 1) & 1][0];
        const float* hbase = hsrc + hoff;

        unsigned long long acc[4][3];
#pragma unroll
        for (int i = 0; i < 4; ++i)
#pragma unroll
            for (int g = 0; g < 3; ++g) acc[i][g] = 0ull;

#pragma unroll 4
        for (int k4 = 0; k4 < 32; ++k4) {
            ulonglong2 v0 = wp0[k4];
            ulonglong2 v1 = wp1[k4];
            ulonglong2 v2 = wp2[k4];
#pragma unroll
            for (int i = 0; i < 4; ++i) {
                ulonglong2 hv = ldcg_u2(hbase + i * UU + k4 * 4);
                fma2(acc[i][0], hv.x, v0.x);
                fma2(acc[i][1], hv.x, v1.x);
                fma2(acc[i][2], hv.x, v2.x);
                fma2(acc[i][0], hv.y, v0.y);
                fma2(acc[i][1], hv.y, v1.y);
                fma2(acc[i][2], hv.y, v2.y);
            }
        }

        // write K-split partials (horizontal sum of the f32x2 lanes)
#pragma unroll
        for (int i = 0; i < 4; ++i)
#pragma unroll
            for (int g = 0; g < 3; ++g) {
                float2 v = upk(acc[i][g]);
                red[ks][g][i][bg][c] = v.x + v.y;
            }
        __syncthreads();

        // gate phase: thread (b2, c2) reduces over ks and updates its state
        const int ii = b2 & 3, bgg = b2 >> 2;
        float s0 = red[0][0][ii][bgg][c2] + red[1][0][ii][bgg][c2] +
                   red[2][0][ii][bgg][c2] + red[3][0][ii][bgg][c2];
        float s1 = red[0][1][ii][bgg][c2] + red[1][1][ii][bgg][c2] +
                   red[2][1][ii][bgg][c2] + red[3][1][ii][bgg][c2];
        float s2 = red[0][2][ii][bgg][c2] + red[1][2][ii][bgg][c2] +
                   red[2][2][ii][bgg][c2] + red[3][2][ii][bgg][c2];

        float ig = fsig(pi + s0);
        float fg = fsig(pf + s1);
        float cin = ftanh(pc + s2);
        cst = fg * cst + ig * cin;
        float hn = ftanh(cst);

        g_hbuf[t & 1][b2 * UU + u] = hn;
        orow[(size_t)t * UU] = hn;

        if (t < TT - 1) {
            __threadfence();           // release h writes to L2 device-wide
            __syncthreads();           // also guards red[] reuse next step
            if (tid == 0) {
                atomicAdd(&g_count, 1u);
                unsigned target = (unsigned)(t + 1) * NCTA;
                while (*(volatile unsigned*)&g_count < target) { }
            }
            __syncthreads();
        } else {
            __syncthreads();           // red[] not reused, but keep uniform exit
        }
    }
}

extern "C" void kernel_launch(void* const* d_in, const int* in_sizes, int n_in,
                              void* d_out, int out_size) {
    const float* x   = (const float*)d_in[0];
    const float* wxi = (const float*)d_in[1];
    const float* wxf = (const float*)d_in[2];
    const float* wxc = (const float*)d_in[3];
    const float* whi = (const float*)d_in[4];
    const float* whf = (const float*)d_in[5];
    const float* whc = (const float*)d_in[6];
    const float* bi  = (const float*)d_in[7];
    const float* bf  = (const float*)d_in[8];
    const float* bc  = (const float*)d_in[9];
    const float* h0  = (const float*)d_in[10];
    const float* c0  = (const float*)d_in[11];
    float* out = (float*)d_out;

    proj_kernel<<<dim3(8, TT), 256>>>(x, wxi, wxf, wxc, bi, bf, bc);
    lstm_kernel<<<NCTA, 256>>>(whi, whf, whc, h0, c0, out);
}

// round 3
// speedup vs baseline: 2.2124x; 1.8124x over previous
#include <cuda_runtime.h>
#include <cstdint>

#define BB 64
#define TT 512
#define DD 256
#define UU 512
#define NCTA 128
#define WROW 520   // weight row stride (floats): 520*4 % 128 == 32 -> 4 c-rows distinct

// smem layout (dynamic)
#define SMEM_H_BYTES (64 * 2048)                 // h staging: [64][512] floats, swizzled
#define SMEM_W_OFF   SMEM_H_BYTES
#define SMEM_W_BYTES (3 * 4 * WROW * 4)          // 24960
#define SMEM_R_OFF   (SMEM_W_OFF + SMEM_W_BYTES)
#define SMEM_R_BYTES (4 * 3 * 4 * 16 * 5 * 4)    // 15360
#define SMEM_TOTAL   (SMEM_R_OFF + SMEM_R_BYTES) // ~171 KB

// Scratch (static device arrays; no cudaMalloc anywhere).
__device__ float g_xp[3][TT][BB][UU];     // input projections, time-major [g][t][b][u]
__device__ float g_hbuf[2][BB * UU];      // ping-pong hidden state
__device__ unsigned g_count;              // grid barrier counter (reset each launch)

// ---- packed f32x2 helpers (full-rate fp32 on sm_103a) ----
__device__ __forceinline__ void fma2(unsigned long long &d, unsigned long long a,
                                     unsigned long long b) {
    asm("fma.rn.f32x2 %0, %1, %2, %0;" : "+l"(d) : "l"(a), "l"(b));
}
__device__ __forceinline__ float2 upk(unsigned long long v) {
    float2 r;
    asm("mov.b64 {%0, %1}, %2;" : "=f"(r.x), "=f"(r.y) : "l"(v));
    return r;
}
__device__ __forceinline__ void cp16(uint32_t dst, const float* src) {
    asm volatile("cp.async.cg.shared.global [%0], [%1], 16;" :: "r"(dst), "l"(src));
}

__device__ __forceinline__ float fsig(float x) {
    return __fdividef(1.0f, 1.0f + __expf(-x));
}
__device__ __forceinline__ float ftanh(float x) {
    float e = __expf(-2.0f * fabsf(x));
    float r = __fdividef(1.0f - e, 1.0f + e);
    return copysignf(r, x);
}

// ============================================================================
// Phase 1: xp[g][t][b][u] = x[b,t,:] @ w_xg[:,u] + b_g[u]   (unchanged)
// ============================================================================
__global__ void __launch_bounds__(256, 2) proj_kernel(
    const float* __restrict__ x,
    const float* __restrict__ wxi, const float* __restrict__ wxf,
    const float* __restrict__ wxc,
    const float* __restrict__ bi, const float* __restrict__ bf,
    const float* __restrict__ bc) {
    __shared__ __align__(16) float xs[64][33];
    __shared__ __align__(16) float ws[3][32][64];

    const int tid = threadIdx.x;
    const int t = blockIdx.y;
    const int ub = blockIdx.x * 64;

    if (blockIdx.x == 0 && blockIdx.y == 0 && tid == 0) g_count = 0u;

    const int ug = tid & 15;
    const int bg = tid >> 4;
    const int ul = ug << 2;
    const int b0 = bg << 2;

    unsigned long long acc[3][4][2];
#pragma unroll
    for (int g = 0; g < 3; ++g)
#pragma unroll
        for (int i = 0; i < 4; ++i) { acc[g][i][0] = 0ull; acc[g][i][1] = 0ull; }

    for (int k0 = 0; k0 < DD; k0 += 32) {
#pragma unroll
        for (int i = 0; i < 8; ++i) {
            int idx = tid + i * 256;
            int bb = idx >> 5, kk = idx & 31;
            xs[bb][kk] = x[(bb * TT + t) * DD + k0 + kk];
        }
#pragma unroll
        for (int i = 0; i < 24; ++i) {
            int idx = tid + i * 256;
            int g = idx >> 11, r = idx & 2047, kk = r >> 6, uu = r & 63;
            const float* w = (g == 0) ? wxi : ((g == 1) ? wxf : wxc);
            ws[g][kk][uu] = w[(k0 + kk) * UU + ub + uu];
        }
        __syncthreads();
#pragma unroll
        for (int kk = 0; kk < 32; ++kk) {
            unsigned long long xb[4];
#pragma unroll
            for (int i = 0; i < 4; ++i) {
                unsigned xv = __float_as_uint(xs[b0 + i][kk]);
                asm("mov.b64 %0, {%1, %1};" : "=l"(xb[i]) : "r"(xv));
            }
#pragma unroll
            for (int g = 0; g < 3; ++g) {
                const ulonglong2 wv = *(const ulonglong2*)&ws[g][kk][ul];
#pragma unroll
                for (int i = 0; i < 4; ++i) {
                    fma2(acc[g][i][0], xb[i], wv.x);
                    fma2(acc[g][i][1], xb[i], wv.y);
                }
            }
        }
        __syncthreads();
    }

    const float* biases[3] = {bi, bf, bc};
#pragma unroll
    for (int g = 0; g < 3; ++g) {
        float2 bv0 = *(const float2*)&biases[g][ub + ul];
        float2 bv1 = *(const float2*)&biases[g][ub + ul + 2];
#pragma unroll
        for (int i = 0; i < 4; ++i) {
            float2 r0 = upk(acc[g][i][0]);
            float2 r1 = upk(acc[g][i][1]);
            r0.x += bv0.x; r0.y += bv0.y;
            r1.x += bv1.x; r1.y += bv1.y;
            float* dst = &g_xp[g][t][b0 + i][ub + ul];
            *(float2*)dst = r0;
            *(float2*)(dst + 2) = r1;
        }
    }
}

// ============================================================================
// Phase 2: persistent recurrent kernel with smem-staged h (cp.async + swizzle).
// 128 CTAs x 256 threads. CTA owns 4 U-columns x 3 gates.
// k-loop role: c = tid&3 (column, 4-way smem broadcast),
//              bg = (tid>>2)&15 (4 b-rows), ks = tid>>6;
//              each thread covers k in [ks*64, ks*64+64) U [256+ks*64, ...).
// h smem layout: row r at r*2048 bytes; 16B slot j stored at slot j^( (r>>2)&7 )
//   -> compute-side LDS.128 (8 rows x 4-way bcast) is single-phase.
// ============================================================================
__global__ void __launch_bounds__(256, 1) lstm_kernel(
    const float* __restrict__ whi, const float* __restrict__ whf,
    const float* __restrict__ whc,
    const float* __restrict__ h0, const float* __restrict__ c0,
    float* __restrict__ out) {
    extern __shared__ __align__(16) char sm[];
    float* smW = (float*)(sm + SMEM_W_OFF);
    float* smR = (float*)(sm + SMEM_R_OFF);

    const int tid = threadIdx.x;
    const int u0 = blockIdx.x * 4;
    // k-loop roles
    const int c  = tid & 3;
    const int bg = (tid >> 2) & 15;
    const int ks = tid >> 6;
    // gate roles
    const int b2 = tid >> 2;
    const int c2 = tid & 3;
    const int u  = u0 + c2;

    {
        const float* wsrc[3] = {whi, whf, whc};
#pragma unroll
        for (int g = 0; g < 3; ++g)
            for (int i = tid; i < 4 * UU; i += 256) {
                int cc = i & 3, k = i >> 2;
                smW[(g * 4 + cc) * WROW + k] = wsrc[g][k * UU + u0 + cc];
            }
    }
    float cst = c0[b2 * UU + u];

    const uint32_t smh_base = (uint32_t)__cvta_generic_to_shared(sm);
    const uint32_t bgx = (uint32_t)((bg & 7) << 4);       // swizzle key (bytes)
    const char* hrow[4];
#pragma unroll
    for (int i = 0; i < 4; ++i) hrow[i] = sm + (bg * 4 + i) * 2048;
    const float* wpc0 = smW + (0 * 4 + c) * WROW + ks * 64;
    const float* wpc1 = smW + (1 * 4 + c) * WROW + ks * 64;
    const float* wpc2 = smW + (2 * 4 + c) * WROW + ks * 64;

    const float* xpi = &g_xp[0][0][b2][u];
    const float* xpf = &g_xp[1][0][b2][u];
    const float* xpc = &g_xp[2][0][b2][u];
    float* orow = out + (size_t)(b2 * TT) * UU + u;
    // reduction slot for this thread's partial write: red[ks][g][i][bg][c]
    float* redw = smR + ((ks * 3) * 4 * 16 * 5) + bg * 5 + c;
    // gate-phase read base: red[.][g][b2&3][b2>>2][c2]
    const float* redr = smR + ((b2 & 3) * 16 * 5) + (b2 >> 2) * 5 + c2;

    __syncthreads();

    for (int t = 0; t < TT; ++t) {
        // prefetch this thread's input projections (gate role)
        float pi = __ldcg(xpi + t * (BB * UU));
        float pf = __ldcg(xpf + t * (BB * UU));
        float pc = __ldcg(xpc + t * (BB * UU));

        const float* hsrc = (t == 0) ? h0 : &g_hbuf[(t + 1) & 1][0];

        // stage h -> smem in two K-halves (64 KB each)
#pragma unroll
        for (int half = 0; half < 2; ++half) {
#pragma unroll
            for (int it = 0; it < 16; ++it) {
                int idx = it * 256 + tid;            // [0, 4096)
                int r = idx >> 6;                    // row
                int j = half * 64 + (idx & 63);      // 16B slot in row
                uint32_t daddr = smh_base + r * 2048 +
                                 (uint32_t)((j << 4) ^ (((r >> 2) & 7) << 4));
                cp16(daddr, hsrc + r * 512 + j * 4);
            }
            asm volatile("cp.async.commit_group;");
        }

        unsigned long long acc[4][3];
#pragma unroll
        for (int i = 0; i < 4; ++i)
#pragma unroll
            for (int g = 0; g < 3; ++g) acc[i][g] = 0ull;

#pragma unroll
        for (int p = 0; p < 2; ++p) {
            if (p == 0) { asm volatile("cp.async.wait_group 1;"); }
            else        { asm volatile("cp.async.wait_group 0;"); }
            __syncthreads();

            const int wk = p * 256;                 // weight k offset
            const uint32_t jb = (uint32_t)(p * 1024 + ks * 256);  // byte offset in row
#pragma unroll
            for (int k4 = 0; k4 < 16; ++k4) {
                const ulonglong2 v0 = *(const ulonglong2*)(wpc0 + wk + k4 * 4);
                const ulonglong2 v1 = *(const ulonglong2*)(wpc1 + wk + k4 * 4);
                const ulonglong2 v2 = *(const ulonglong2*)(wpc2 + wk + k4 * 4);
                const uint32_t hoff = jb + (uint32_t)((k4 << 4) ^ bgx);
#pragma unroll
                for (int i = 0; i < 4; ++i) {
                    const ulonglong2 hv = *(const ulonglong2*)(hrow[i] + hoff);
                    fma2(acc[i][0], hv.x, v0.x);
                    fma2(acc[i][1], hv.x, v1.x);
                    fma2(acc[i][2], hv.x, v2.x);
                    fma2(acc[i][0], hv.y, v0.y);
                    fma2(acc[i][1], hv.y, v1.y);
                    fma2(acc[i][2], hv.y, v2.y);
                }
            }
        }

        // write K-split partials (horizontal sum of the f32x2 lanes)
#pragma unroll
        for (int i = 0; i < 4; ++i)
#pragma unroll
            for (int g = 0; g < 3; ++g) {
                float2 v = upk(acc[i][g]);
                redw[(g * 4 + i) * (16 * 5)] = v.x + v.y;
            }
        __syncthreads();

        // gate phase: thread (b2, c2) reduces over ks and updates its state
        float s0 = 0.f, s1 = 0.f, s2 = 0.f;
#pragma unroll
        for (int kk = 0; kk < 4; ++kk) {
            const float* rb = redr + kk * (3 * 4 * 16 * 5);
            s0 += rb[0 * (4 * 16 * 5)];
            s1 += rb[1 * (4 * 16 * 5)];
            s2 += rb[2 * (4 * 16 * 5)];
        }

        float ig = fsig(pi + s0);
        float fg = fsig(pf + s1);
        float cin = ftanh(pc + s2);
        cst = fg * cst + ig * cin;
        float hn = ftanh(cst);

        g_hbuf[t & 1][b2 * UU + u] = hn;
        orow[(size_t)t * UU] = hn;

        if (t < TT - 1) {
            __syncthreads();                 // all h stores done CTA-wide
            if (tid == 0) {
                unsigned prev;
                asm volatile("atom.add.release.gpu.u32 %0, [%1], 1;"
                             : "=r"(prev) : "l"(&g_count) : "memory");
                unsigned target = (unsigned)(t + 1) * NCTA;
                unsigned v;
                do {
                    asm volatile("ld.acquire.gpu.u32 %0, [%1];"
                                 : "=r"(v) : "l"(&g_count) : "memory");
                } while (v < target);
            }
            __syncthreads();                 // release CTA; also guards smem reuse
        }
    }
}

extern "C" void kernel_launch(void* const* d_in, const int* in_sizes, int n_in,
                              void* d_out, int out_size) {
    const float* x   = (const float*)d_in[0];
    const float* wxi = (const float*)d_in[1];
    const float* wxf = (const float*)d_in[2];
    const float* wxc = (const float*)d_in[3];
    const float* whi = (const float*)d_in[4];
    const float* whf = (const float*)d_in[5];
    const float* whc = (const float*)d_in[6];
    const float* bi  = (const float*)d_in[7];
    const float* bf  = (const float*)d_in[8];
    const float* bc  = (const float*)d_in[9];
    const float* h0  = (const float*)d_in[10];
    const float* c0  = (const float*)d_in[11];
    float* out = (float*)d_out;

    cudaFuncSetAttribute(lstm_kernel, cudaFuncAttributeMaxDynamicSharedMemorySize,
                         SMEM_TOTAL);

    proj_kernel<<<dim3(8, TT), 256>>>(x, wxi, wxf, wxc, bi, bf, bc);
    lstm_kernel<<<NCTA, 256, SMEM_TOTAL>>>(whi, whf, whc, h0, c0, out);
}